// round 6
// baseline (speedup 1.0000x reference)
#include <cuda_runtime.h>
#include <cuda_bf16.h>
#include <cstdint>

#define SEQ   2048
#define BATCH 2
#define NH    16
#define HD    64
#define DM    1024
#define WIN   256
#define MROWS (BATCH * SEQ)          // 4096

// ---------------------------------------------------------------------------
// Device scratch (allocation-guard-legal). All activations kept as split bf16.
// ---------------------------------------------------------------------------
__device__ __nv_bfloat16 g_xh[(size_t)MROWS * DM];
__device__ __nv_bfloat16 g_xl[(size_t)MROWS * DM];
__device__ __nv_bfloat16 g_Ch[(size_t)MROWS * DM];
__device__ __nv_bfloat16 g_Cl[(size_t)MROWS * DM];
__device__ __nv_bfloat16 g_Qh[(size_t)MROWS * DM];
__device__ __nv_bfloat16 g_Ql[(size_t)MROWS * DM];
__device__ __nv_bfloat16 g_Kh[(size_t)MROWS * DM];
__device__ __nv_bfloat16 g_Kl[(size_t)MROWS * DM];
__device__ __nv_bfloat16 g_Vh[(size_t)MROWS * DM];
__device__ __nv_bfloat16 g_Vl[(size_t)MROWS * DM];
__device__ __nv_bfloat16 g_Bh[(size_t)4 * DM * DM];   // W^T as [n][k]; q,k,v,o
__device__ __nv_bfloat16 g_Bl[(size_t)4 * DM * DM];

// ---------------------------------------------------------------------------
// PTX helpers (portable: sm_80+ tensor path, cp.async)
// ---------------------------------------------------------------------------
__device__ __forceinline__ uint32_t smem_u32(const void* p) {
    uint32_t a;
    asm("{ .reg .u64 t; cvta.to.shared.u64 t, %1; cvt.u32.u64 %0, t; }"
        : "=r"(a) : "l"(p));
    return a;
}

__device__ __forceinline__ void cpasync16(uint32_t dst, const void* src) {
    asm volatile("cp.async.cg.shared.global [%0], [%1], 16;"
                 :: "r"(dst), "l"(src));
}
#define CP_COMMIT() asm volatile("cp.async.commit_group;" ::: "memory")
#define CP_WAIT(n)  asm volatile("cp.async.wait_group %0;" :: "n"(n) : "memory")

__device__ __forceinline__ void ldsm4(uint32_t* r, uint32_t addr) {
    asm volatile("ldmatrix.sync.aligned.m8n8.x4.shared.b16 {%0,%1,%2,%3}, [%4];"
                 : "=r"(r[0]), "=r"(r[1]), "=r"(r[2]), "=r"(r[3]) : "r"(addr));
}
__device__ __forceinline__ void ldsm4t(uint32_t* r, uint32_t addr) {
    asm volatile("ldmatrix.sync.aligned.m8n8.x4.trans.shared.b16 {%0,%1,%2,%3}, [%4];"
                 : "=r"(r[0]), "=r"(r[1]), "=r"(r[2]), "=r"(r[3]) : "r"(addr));
}

__device__ __forceinline__ void mma16816(float* c, const uint32_t* a, const uint32_t* b) {
    asm volatile(
        "mma.sync.aligned.m16n8k16.row.col.f32.bf16.bf16.f32 "
        "{%0,%1,%2,%3}, {%4,%5,%6,%7}, {%8,%9}, {%0,%1,%2,%3};"
        : "+f"(c[0]), "+f"(c[1]), "+f"(c[2]), "+f"(c[3])
        : "r"(a[0]), "r"(a[1]), "r"(a[2]), "r"(a[3]), "r"(b[0]), "r"(b[1]));
}

__device__ __forceinline__ uint32_t pkhi(float a, float b) {
    __nv_bfloat162 t = __floats2bfloat162_rn(a, b);
    return *reinterpret_cast<uint32_t*>(&t);
}
__device__ __forceinline__ uint32_t pklo(float a, float b, uint32_t hi) {
    __nv_bfloat162 h = *reinterpret_cast<__nv_bfloat162*>(&hi);
    return pkhi(a - __bfloat162float(h.x), b - __bfloat162float(h.y));
}

// ---------------------------------------------------------------------------
// Split fp32 x -> bf16 hi/lo
// ---------------------------------------------------------------------------
__global__ __launch_bounds__(256) void split_kernel(const float* __restrict__ src)
{
    int i = blockIdx.x * 256 + threadIdx.x;
    float4 v = ((const float4*)src)[i];
    uint32_t h01 = pkhi(v.x, v.y);
    uint32_t h23 = pkhi(v.z, v.w);
    ((uint32_t*)g_xh)[2 * i]     = h01;
    ((uint32_t*)g_xh)[2 * i + 1] = h23;
    ((uint32_t*)g_xl)[2 * i]     = pklo(v.x, v.y, h01);
    ((uint32_t*)g_xl)[2 * i + 1] = pklo(v.z, v.w, h23);
}

// Split + transpose weights: g_B*[z][n][k] = W_z[k][n]
__global__ __launch_bounds__(256) void splitT_kernel(
    const float* __restrict__ w0, const float* __restrict__ w1,
    const float* __restrict__ w2, const float* __restrict__ w3)
{
    __shared__ float t[32][33];
    const int z = blockIdx.z;
    const float* __restrict__ W = (z == 0) ? w0 : (z == 1) ? w1 : (z == 2) ? w2 : w3;
    const int tx = threadIdx.x, ty = threadIdx.y;
    const int bx = blockIdx.x, by = blockIdx.y;
#pragma unroll
    for (int i = 0; i < 4; i++) {
        int k = by * 32 + ty + i * 8;
        int n = bx * 32 + tx;
        t[ty + i * 8][tx] = W[(size_t)k * DM + n];
    }
    __syncthreads();
    size_t base = (size_t)z * DM * DM;
#pragma unroll
    for (int i = 0; i < 4; i++) {
        int n = bx * 32 + ty + i * 8;
        int k = by * 32 + tx;
        float v = t[tx][ty + i * 8];
        __nv_bfloat16 h = __float2bfloat16(v);
        g_Bh[base + (size_t)n * DM + k] = h;
        g_Bl[base + (size_t)n * DM + k] = __float2bfloat16(v - __bfloat162float(h));
    }
}

// ---------------------------------------------------------------------------
// Split-bf16 HMMA GEMM. CTA 128x128, kTile 32, 3-stage cp.async pipeline,
// one barrier per iteration. 8 warps of 64x32.
// mode 0: x -> Qh/Ql, Kh/Kl, Vh/Vl (Q scaled 1/8). mode 1: C -> out (+bias).
// ---------------------------------------------------------------------------
#define MMBUF   10240                      // 128 rows * 80 B
#define MMSTAGE (4 * MMBUF)                // Ah, Al, Bh, Bl  (40960)
#define MM_SMEM (3 * MMSTAGE)              // 122880

__global__ __launch_bounds__(256, 1) void mm_kernel(
    const float* __restrict__ bias, float* __restrict__ outp, int mode)
{
    extern __shared__ char smc[];
    const uint32_t sm0 = smem_u32(smc);
    const int tid  = threadIdx.x;
    const int lane = tid & 31;
    const int wid  = tid >> 5;
    const int warpM = wid & 1;
    const int warpN = wid >> 1;
    const int row0 = blockIdx.y * 128;
    const int col0 = blockIdx.x * 128;
    const int z    = blockIdx.z;
    const int zz   = (mode == 0) ? z : 3;

    const __nv_bfloat16* __restrict__ Ah = (mode == 0) ? g_xh : g_Ch;
    const __nv_bfloat16* __restrict__ Al = (mode == 0) ? g_xl : g_Cl;
    const __nv_bfloat16* __restrict__ Bh = g_Bh + (size_t)zz * DM * DM;
    const __nv_bfloat16* __restrict__ Bl = g_Bl + (size_t)zz * DM * DM;

    float acc[4][4][4];
#pragma unroll
    for (int a = 0; a < 4; a++)
#pragma unroll
        for (int b = 0; b < 4; b++)
#pragma unroll
            for (int c = 0; c < 4; c++) acc[a][b][c] = 0.f;

    const int a_r  = (lane & 7) + ((lane >> 3) & 1) * 8;
    const int a_kc = (lane >> 4) * 8;
    const int b_n  = (lane & 7) + (lane >> 4) * 8;
    const int b_kc = ((lane >> 3) & 1) * 8;

#define LOAD_STAGE(it_)                                                          \
    do {                                                                         \
        int k0_ = (it_) * 32;                                                    \
        uint32_t sb_ = sm0 + ((it_) % 3) * MMSTAGE;                              \
        _Pragma("unroll")                                                        \
        for (int i_ = 0; i_ < 2; i_++) {                                         \
            int idx_ = tid + i_ * 256;                                           \
            int r_ = idx_ >> 2, sg_ = idx_ & 3;                                  \
            uint32_t doff_ = r_ * 80 + sg_ * 16;                                 \
            cpasync16(sb_ + doff_,              Ah + (size_t)(row0 + r_) * DM + k0_ + sg_ * 8); \
            cpasync16(sb_ + MMBUF + doff_,      Al + (size_t)(row0 + r_) * DM + k0_ + sg_ * 8); \
            cpasync16(sb_ + 2 * MMBUF + doff_,  Bh + (size_t)(col0 + r_) * DM + k0_ + sg_ * 8); \
            cpasync16(sb_ + 3 * MMBUF + doff_,  Bl + (size_t)(col0 + r_) * DM + k0_ + sg_ * 8); \
        }                                                                        \
    } while (0)

    LOAD_STAGE(0);
    CP_COMMIT();
    LOAD_STAGE(1);
    CP_COMMIT();

    for (int it = 0; it < 32; it++) {
        if (it < 31) { CP_WAIT(1); } else { CP_WAIT(0); }
        __syncthreads();                 // stage it visible; all warps done compute(it-1)
        if (it + 2 < 32) {
            LOAD_STAGE(it + 2);          // overwrites buffer last read at compute(it-1): safe
            CP_COMMIT();
        }

        uint32_t sb = sm0 + (it % 3) * MMSTAGE;
#pragma unroll
        for (int kk = 0; kk < 2; kk++) {
            uint32_t ah[4][4], al[4][4], bh[2][4], bl[2][4];
#pragma unroll
            for (int mb = 0; mb < 4; mb++) {
                int r = warpM * 64 + mb * 16 + a_r;
                uint32_t off = (uint32_t)(r * 80 + (kk * 16 + a_kc) * 2);
                ldsm4(ah[mb], sb + off);
                ldsm4(al[mb], sb + MMBUF + off);
            }
#pragma unroll
            for (int np = 0; np < 2; np++) {
                int n = warpN * 32 + np * 16 + b_n;
                uint32_t off = (uint32_t)(n * 80 + (kk * 16 + b_kc) * 2);
                ldsm4(bh[np], sb + 2 * MMBUF + off);
                ldsm4(bl[np], sb + 3 * MMBUF + off);
            }
#pragma unroll
            for (int mb = 0; mb < 4; mb++)
#pragma unroll
                for (int nb = 0; nb < 4; nb++) {
                    const uint32_t* bhf = &bh[nb >> 1][(nb & 1) * 2];
                    const uint32_t* blf = &bl[nb >> 1][(nb & 1) * 2];
                    mma16816(acc[mb][nb], ah[mb], bhf);
                    mma16816(acc[mb][nb], ah[mb], blf);
                    mma16816(acc[mb][nb], al[mb], bhf);
                }
        }
    }

    if (mode == 0) {
        __nv_bfloat16* __restrict__ Oh = (z == 0) ? g_Qh : (z == 1) ? g_Kh : g_Vh;
        __nv_bfloat16* __restrict__ Ol = (z == 0) ? g_Ql : (z == 1) ? g_Kl : g_Vl;
        const float sc = (z == 0) ? 0.125f : 1.0f;
#pragma unroll
        for (int mb = 0; mb < 4; mb++) {
            int r = row0 + warpM * 64 + mb * 16 + (lane >> 2);
#pragma unroll
            for (int nb = 0; nb < 4; nb++) {
                int c = col0 + warpN * 32 + nb * 8 + (lane & 3) * 2;
                float v0 = acc[mb][nb][0] * sc, v1 = acc[mb][nb][1] * sc;
                float v2 = acc[mb][nb][2] * sc, v3 = acc[mb][nb][3] * sc;
                uint32_t h01 = pkhi(v0, v1);
                uint32_t h23 = pkhi(v2, v3);
                *(uint32_t*)&Oh[(size_t)r * DM + c]       = h01;
                *(uint32_t*)&Ol[(size_t)r * DM + c]       = pklo(v0, v1, h01);
                *(uint32_t*)&Oh[(size_t)(r + 8) * DM + c] = h23;
                *(uint32_t*)&Ol[(size_t)(r + 8) * DM + c] = pklo(v2, v3, h23);
            }
        }
    } else {
#pragma unroll
        for (int mb = 0; mb < 4; mb++) {
            int r = row0 + warpM * 64 + mb * 16 + (lane >> 2);
#pragma unroll
            for (int nb = 0; nb < 4; nb++) {
                int c = col0 + warpN * 32 + nb * 8 + (lane & 3) * 2;
                float2 v0 = make_float2(acc[mb][nb][0] + bias[c], acc[mb][nb][1] + bias[c + 1]);
                float2 v1 = make_float2(acc[mb][nb][2] + bias[c], acc[mb][nb][3] + bias[c + 1]);
                *(float2*)&outp[(size_t)r * DM + c]       = v0;
                *(float2*)&outp[(size_t)(r + 8) * DM + c] = v1;
            }
        }
    }
#undef LOAD_STAGE
}

// ---------------------------------------------------------------------------
// HMMA flash attention, split-bf16 (3-term), cp.async double-buffered K/V.
// Block 128 thr = 4 warps, 64-query tile; warp w owns rows w*16..w*16+15.
// Writes Ch/Cl (split bf16).
// Smem layout (units of ATILE = 64x72 bf16): [Qh][Ql][Kh0][Kh1][Kl0][Kl1][Vh0][Vh1][Vl0][Vl1]
// ---------------------------------------------------------------------------
#define KST 72
#define ATILE (64 * KST)
#define ATB   (ATILE * 2)                        // bytes per tile (9216)
#define ATTN_SMEM (10 * ATB)                     // 92160

__global__ __launch_bounds__(128) void attn_kernel()
{
    extern __shared__ __nv_bfloat16 smb[];
    const uint32_t sm0 = smem_u32(smb);

    const int qt = blockIdx.x;
    const int bh = blockIdx.y;
    const int b  = bh >> 4;
    const int h  = bh & 15;
    const int tid  = threadIdx.x;
    const int w    = tid >> 5;
    const int lane = tid & 31;
    const int qs = qt * 64;

    const size_t hoff = (size_t)b * SEQ * DM + h * HD;
    const __nv_bfloat16* __restrict__ Qgh = g_Qh + hoff;
    const __nv_bfloat16* __restrict__ Qgl = g_Ql + hoff;
    const __nv_bfloat16* __restrict__ Kgh = g_Kh + hoff;
    const __nv_bfloat16* __restrict__ Kgl = g_Kl + hoff;
    const __nv_bfloat16* __restrict__ Vgh = g_Vh + hoff;
    const __nv_bfloat16* __restrict__ Vgl = g_Vl + hoff;

    int ks0 = qs - WIN; if (ks0 < 0) ks0 = 0;
    int ke  = qs + 64 + WIN; if (ke > SEQ) ke = SEQ;
    const int nc = (ke - ks0) >> 6;

    // prefetch chunk 0 (stage 0) while we set up Q
#define PREF(ci_)                                                                \
    do {                                                                         \
        int kb_ = ks0 + (ci_) * 64;                                              \
        uint32_t st_ = ((ci_) & 1) * ATB;                                        \
        _Pragma("unroll")                                                        \
        for (int i_ = 0; i_ < 4; i_++) {                                         \
            int idx_ = tid + i_ * 128;                                           \
            int r_ = idx_ >> 3, c_ = idx_ & 7;                                   \
            uint32_t doff_ = (uint32_t)(r_ * KST + c_ * 8) * 2;                  \
            size_t g_ = (size_t)(kb_ + r_) * DM + c_ * 8;                        \
            cpasync16(sm0 + 2 * ATB + st_ + doff_, Kgh + g_);                    \
            cpasync16(sm0 + 4 * ATB + st_ + doff_, Kgl + g_);                    \
            cpasync16(sm0 + 6 * ATB + st_ + doff_, Vgh + g_);                    \
            cpasync16(sm0 + 8 * ATB + st_ + doff_, Vgl + g_);                    \
        }                                                                        \
    } while (0)

    PREF(0);
    CP_COMMIT();

    // load Q tile (64 rows x 64 bf16)
    for (int i = tid; i < 64 * 8; i += 128) {
        int r = i >> 3, c = i & 7;
        *(uint4*)&smb[r * KST + c * 8]         = *(const uint4*)(Qgh + (size_t)(qs + r) * DM + c * 8);
        *(uint4*)&smb[ATILE + r * KST + c * 8] = *(const uint4*)(Qgl + (size_t)(qs + r) * DM + c * 8);
    }
    __syncthreads();

    const int a_r  = (lane & 7) + ((lane >> 3) & 1) * 8;
    const int a_kc = (lane >> 4) * 8;
    uint32_t qa_h[4][4], qa_l[4][4];
#pragma unroll
    for (int kk = 0; kk < 4; kk++) {
        uint32_t off = (uint32_t)((w * 16 + a_r) * KST + kk * 16 + a_kc) * 2;
        ldsm4(qa_h[kk], sm0 + off);
        ldsm4(qa_l[kk], sm0 + ATB + off);
    }

    float O[8][4];
#pragma unroll
    for (int t = 0; t < 8; t++)
#pragma unroll
        for (int e = 0; e < 4; e++) O[t][e] = 0.f;
    float m0 = -1e30f, m1 = -1e30f, l0 = 0.f, l1 = 0.f;

    const int b_n  = (lane & 7) + (lane >> 4) * 8;
    const int b_kc = ((lane >> 3) & 1) * 8;
    const int v_r  = lane & 15;
    const int v_c  = (lane >> 4) * 8;
    const int q0 = qs + w * 16 + (lane >> 2);
    const int q1 = q0 + 8;

    for (int ci = 0; ci < nc; ci++) {
        const int kb = ks0 + ci * 64;
        __syncthreads();                      // all warps done with stage (ci+1)&1 readers
        if (ci + 1 < nc) {
            PREF(ci + 1);
            CP_COMMIT();
            CP_WAIT(1);                       // chunk ci complete
        } else {
            CP_WAIT(0);
        }
        __syncthreads();                      // chunk ci visible to all

        const uint32_t Khb = sm0 + 2 * ATB + (ci & 1) * ATB;
        const uint32_t Klb = sm0 + 4 * ATB + (ci & 1) * ATB;
        const uint32_t Vhb = sm0 + 6 * ATB + (ci & 1) * ATB;
        const uint32_t Vlb = sm0 + 8 * ATB + (ci & 1) * ATB;

        // ---- scores
        float S[8][4];
#pragma unroll
        for (int t = 0; t < 8; t++)
#pragma unroll
            for (int e = 0; e < 4; e++) S[t][e] = 0.f;

#pragma unroll
        for (int kk = 0; kk < 4; kk++) {
#pragma unroll
            for (int nt = 0; nt < 4; nt++) {
                uint32_t kh[4], kl[4];
                uint32_t off = (uint32_t)((nt * 16 + b_n) * KST + kk * 16 + b_kc) * 2;
                ldsm4(kh, Khb + off);
                ldsm4(kl, Klb + off);
#pragma unroll
                for (int half = 0; half < 2; half++) {
                    float* s = S[nt * 2 + half];
                    mma16816(s, qa_h[kk], &kh[half * 2]);
                    mma16816(s, qa_h[kk], &kl[half * 2]);
                    mma16816(s, qa_l[kk], &kh[half * 2]);
                }
            }
        }

        // ---- mask + online softmax
        const int kc = kb + 2 * (lane & 3);
        float mx0 = -1e30f, mx1 = -1e30f;
#pragma unroll
        for (int j = 0; j < 8; j++) {
            int d0 = kc + j * 8 - q0 + WIN;
            S[j][0] = ((unsigned)d0 <= 2u * WIN)       ? S[j][0] : -1e30f;
            S[j][1] = ((unsigned)(d0 + 1) <= 2u * WIN) ? S[j][1] : -1e30f;
            S[j][2] = ((unsigned)(d0 - 8) <= 2u * WIN) ? S[j][2] : -1e30f;
            S[j][3] = ((unsigned)(d0 - 7) <= 2u * WIN) ? S[j][3] : -1e30f;
            mx0 = fmaxf(mx0, fmaxf(S[j][0], S[j][1]));
            mx1 = fmaxf(mx1, fmaxf(S[j][2], S[j][3]));
        }
        mx0 = fmaxf(mx0, __shfl_xor_sync(0xffffffffu, mx0, 1));
        mx0 = fmaxf(mx0, __shfl_xor_sync(0xffffffffu, mx0, 2));
        mx1 = fmaxf(mx1, __shfl_xor_sync(0xffffffffu, mx1, 1));
        mx1 = fmaxf(mx1, __shfl_xor_sync(0xffffffffu, mx1, 2));

        float mn0 = fmaxf(m0, mx0), mn1 = fmaxf(m1, mx1);
        float f0 = __expf(m0 - mn0), f1 = __expf(m1 - mn1);
        float s0 = 0.f, s1 = 0.f;
#pragma unroll
        for (int j = 0; j < 8; j++) {
            S[j][0] = __expf(S[j][0] - mn0);
            S[j][1] = __expf(S[j][1] - mn0);
            S[j][2] = __expf(S[j][2] - mn1);
            S[j][3] = __expf(S[j][3] - mn1);
            s0 += S[j][0] + S[j][1];
            s1 += S[j][2] + S[j][3];
        }
        s0 += __shfl_xor_sync(0xffffffffu, s0, 1);
        s0 += __shfl_xor_sync(0xffffffffu, s0, 2);
        s1 += __shfl_xor_sync(0xffffffffu, s1, 1);
        s1 += __shfl_xor_sync(0xffffffffu, s1, 2);
        l0 = l0 * f0 + s0;  m0 = mn0;
        l1 = l1 * f1 + s1;  m1 = mn1;
#pragma unroll
        for (int t = 0; t < 8; t++) {
            O[t][0] *= f0; O[t][1] *= f0;
            O[t][2] *= f1; O[t][3] *= f1;
        }

        // ---- PV
#pragma unroll
        for (int kk = 0; kk < 4; kk++) {
            uint32_t pa_h[4], pa_l[4];
            const float* sj0 = S[2 * kk];
            const float* sj1 = S[2 * kk + 1];
            pa_h[0] = pkhi(sj0[0], sj0[1]);  pa_l[0] = pklo(sj0[0], sj0[1], pa_h[0]);
            pa_h[1] = pkhi(sj0[2], sj0[3]);  pa_l[1] = pklo(sj0[2], sj0[3], pa_h[1]);
            pa_h[2] = pkhi(sj1[0], sj1[1]);  pa_l[2] = pklo(sj1[0], sj1[1], pa_h[2]);
            pa_h[3] = pkhi(sj1[2], sj1[3]);  pa_l[3] = pklo(sj1[2], sj1[3], pa_h[3]);
#pragma unroll
            for (int nt = 0; nt < 4; nt++) {
                uint32_t vh[4], vl[4];
                uint32_t off = (uint32_t)((kk * 16 + v_r) * KST + nt * 16 + v_c) * 2;
                ldsm4t(vh, Vhb + off);
                ldsm4t(vl, Vlb + off);
#pragma unroll
                for (int half = 0; half < 2; half++) {
                    float* o = O[nt * 2 + half];
                    mma16816(o, pa_h, &vh[half * 2]);
                    mma16816(o, pa_l, &vh[half * 2]);
                    mma16816(o, pa_h, &vl[half * 2]);
                }
            }
        }
    }

    // ---- epilogue
    float inv0 = 1.f / l0, inv1 = 1.f / l1;
#pragma unroll
    for (int t = 0; t < 8; t++) {
        int c = h * HD + t * 8 + 2 * (lane & 3);
        float v0 = O[t][0] * inv0, v1 = O[t][1] * inv0;
        float v2 = O[t][2] * inv1, v3 = O[t][3] * inv1;
        size_t r0o = ((size_t)b * SEQ + q0) * DM + c;
        size_t r1o = ((size_t)b * SEQ + q1) * DM + c;
        uint32_t h01 = pkhi(v0, v1);
        uint32_t h23 = pkhi(v2, v3);
        *(uint32_t*)&g_Ch[r0o] = h01;
        *(uint32_t*)&g_Cl[r0o] = pklo(v0, v1, h01);
        *(uint32_t*)&g_Ch[r1o] = h23;
        *(uint32_t*)&g_Cl[r1o] = pklo(v2, v3, h23);
    }
#undef PREF
}

// ---------------------------------------------------------------------------
extern "C" void kernel_launch(void* const* d_in, const int* in_sizes, int n_in,
                              void* d_out, int out_size)
{
    const float* x  = (const float*)d_in[0];
    const float* Wq = (const float*)d_in[1];
    const float* Wk = (const float*)d_in[2];
    const float* Wv = (const float*)d_in[3];
    const float* Wo = (const float*)d_in[4];
    const float* bo = (const float*)d_in[5];
    float* out = (float*)d_out;

    cudaFuncSetAttribute(mm_kernel, cudaFuncAttributeMaxDynamicSharedMemorySize, MM_SMEM);
    cudaFuncSetAttribute(attn_kernel, cudaFuncAttributeMaxDynamicSharedMemorySize, ATTN_SMEM);

    split_kernel<<<(MROWS * DM) / (4 * 256), 256>>>(x);
    splitT_kernel<<<dim3(DM / 32, DM / 32, 4), dim3(32, 8)>>>(Wq, Wk, Wv, Wo);

    mm_kernel<<<dim3(DM / 128, MROWS / 128, 3), 256, MM_SMEM>>>(nullptr, nullptr, 0);

    attn_kernel<<<dim3(SEQ / 64, BATCH * NH), 128, ATTN_SMEM>>>();

    mm_kernel<<<dim3(DM / 128, MROWS / 128, 1), 256, MM_SMEM>>>(bo, out, 1);
}

// round 7
// speedup vs baseline: 1.1581x; 1.1581x over previous
#include <cuda_runtime.h>
#include <cuda_bf16.h>
#include <cstdint>

#define SEQ   2048
#define BATCH 2
#define NH    16
#define HD    64
#define DM    1024
#define WIN   256
#define MROWS (BATCH * SEQ)          // 4096

// ---------------------------------------------------------------------------
// Device scratch (allocation-guard-legal). All activations kept as split bf16.
// ---------------------------------------------------------------------------
__device__ __nv_bfloat16 g_xh[(size_t)MROWS * DM];
__device__ __nv_bfloat16 g_xl[(size_t)MROWS * DM];
__device__ __nv_bfloat16 g_Ch[(size_t)MROWS * DM];
__device__ __nv_bfloat16 g_Cl[(size_t)MROWS * DM];
__device__ __nv_bfloat16 g_Qh[(size_t)MROWS * DM];
__device__ __nv_bfloat16 g_Ql[(size_t)MROWS * DM];
__device__ __nv_bfloat16 g_Kh[(size_t)MROWS * DM];
__device__ __nv_bfloat16 g_Kl[(size_t)MROWS * DM];
__device__ __nv_bfloat16 g_Vh[(size_t)MROWS * DM];
__device__ __nv_bfloat16 g_Vl[(size_t)MROWS * DM];
__device__ __nv_bfloat16 g_Bh[(size_t)4 * DM * DM];   // W^T as [n][k]; q,k,v,o
__device__ __nv_bfloat16 g_Bl[(size_t)4 * DM * DM];

// ---------------------------------------------------------------------------
// PTX helpers (portable: sm_80+ tensor path, cp.async)
// ---------------------------------------------------------------------------
__device__ __forceinline__ uint32_t smem_u32(const void* p) {
    uint32_t a;
    asm("{ .reg .u64 t; cvta.to.shared.u64 t, %1; cvt.u32.u64 %0, t; }"
        : "=r"(a) : "l"(p));
    return a;
}

__device__ __forceinline__ void cpasync16(uint32_t dst, const void* src) {
    asm volatile("cp.async.cg.shared.global [%0], [%1], 16;"
                 :: "r"(dst), "l"(src));
}
#define CP_COMMIT() asm volatile("cp.async.commit_group;" ::: "memory")
#define CP_WAIT(n)  asm volatile("cp.async.wait_group %0;" :: "n"(n) : "memory")

__device__ __forceinline__ void ldsm4(uint32_t* r, uint32_t addr) {
    asm volatile("ldmatrix.sync.aligned.m8n8.x4.shared.b16 {%0,%1,%2,%3}, [%4];"
                 : "=r"(r[0]), "=r"(r[1]), "=r"(r[2]), "=r"(r[3]) : "r"(addr));
}
__device__ __forceinline__ void ldsm4t(uint32_t* r, uint32_t addr) {
    asm volatile("ldmatrix.sync.aligned.m8n8.x4.trans.shared.b16 {%0,%1,%2,%3}, [%4];"
                 : "=r"(r[0]), "=r"(r[1]), "=r"(r[2]), "=r"(r[3]) : "r"(addr));
}

__device__ __forceinline__ void mma16816(float* c, const uint32_t* a, const uint32_t* b) {
    asm volatile(
        "mma.sync.aligned.m16n8k16.row.col.f32.bf16.bf16.f32 "
        "{%0,%1,%2,%3}, {%4,%5,%6,%7}, {%8,%9}, {%0,%1,%2,%3};"
        : "+f"(c[0]), "+f"(c[1]), "+f"(c[2]), "+f"(c[3])
        : "r"(a[0]), "r"(a[1]), "r"(a[2]), "r"(a[3]), "r"(b[0]), "r"(b[1]));
}

__device__ __forceinline__ uint32_t pkhi(float a, float b) {
    __nv_bfloat162 t = __floats2bfloat162_rn(a, b);
    return *reinterpret_cast<uint32_t*>(&t);
}
__device__ __forceinline__ uint32_t pklo(float a, float b, uint32_t hi) {
    __nv_bfloat162 h = *reinterpret_cast<__nv_bfloat162*>(&hi);
    return pkhi(a - __bfloat162float(h.x), b - __bfloat162float(h.y));
}

// ---------------------------------------------------------------------------
// Split fp32 x -> bf16 hi/lo
// ---------------------------------------------------------------------------
__global__ __launch_bounds__(256) void split_kernel(const float* __restrict__ src)
{
    int i = blockIdx.x * 256 + threadIdx.x;
    float4 v = ((const float4*)src)[i];
    uint32_t h01 = pkhi(v.x, v.y);
    uint32_t h23 = pkhi(v.z, v.w);
    ((uint32_t*)g_xh)[2 * i]     = h01;
    ((uint32_t*)g_xh)[2 * i + 1] = h23;
    ((uint32_t*)g_xl)[2 * i]     = pklo(v.x, v.y, h01);
    ((uint32_t*)g_xl)[2 * i + 1] = pklo(v.z, v.w, h23);
}

// Split + transpose weights: g_B*[z][n][k] = W_z[k][n]
__global__ __launch_bounds__(256) void splitT_kernel(
    const float* __restrict__ w0, const float* __restrict__ w1,
    const float* __restrict__ w2, const float* __restrict__ w3)
{
    __shared__ float t[32][33];
    const int z = blockIdx.z;
    const float* __restrict__ W = (z == 0) ? w0 : (z == 1) ? w1 : (z == 2) ? w2 : w3;
    const int tx = threadIdx.x, ty = threadIdx.y;
    const int bx = blockIdx.x, by = blockIdx.y;
#pragma unroll
    for (int i = 0; i < 4; i++) {
        int k = by * 32 + ty + i * 8;
        int n = bx * 32 + tx;
        t[ty + i * 8][tx] = W[(size_t)k * DM + n];
    }
    __syncthreads();
    size_t base = (size_t)z * DM * DM;
#pragma unroll
    for (int i = 0; i < 4; i++) {
        int n = bx * 32 + ty + i * 8;
        int k = by * 32 + tx;
        float v = t[tx][ty + i * 8];
        __nv_bfloat16 h = __float2bfloat16(v);
        g_Bh[base + (size_t)n * DM + k] = h;
        g_Bl[base + (size_t)n * DM + k] = __float2bfloat16(v - __bfloat162float(h));
    }
}

// ---------------------------------------------------------------------------
// Split-bf16 HMMA GEMM. CTA 128x128, kTile 32, 2-stage cp.async,
// single barrier per iteration (wait -> barrier -> prefetch -> compute).
// __launch_bounds__(256,2): 2 CTAs/SM, regs capped at 128.
// mode 0: x -> Qh/Ql, Kh/Kl, Vh/Vl (Q scaled 1/8). mode 1: C -> out (+bias).
// ---------------------------------------------------------------------------
#define MMBUF   10240                      // 128 rows * 80 B
#define MMSTAGE (4 * MMBUF)                // Ah, Al, Bh, Bl  (40960)
#define MM_SMEM (2 * MMSTAGE)              // 81920

__global__ __launch_bounds__(256, 2) void mm_kernel(
    const float* __restrict__ bias, float* __restrict__ outp, int mode)
{
    extern __shared__ char smc[];
    const uint32_t sm0 = smem_u32(smc);
    const int tid  = threadIdx.x;
    const int lane = tid & 31;
    const int wid  = tid >> 5;
    const int warpM = wid & 1;
    const int warpN = wid >> 1;
    const int row0 = blockIdx.y * 128;
    const int col0 = blockIdx.x * 128;
    const int z    = blockIdx.z;
    const int zz   = (mode == 0) ? z : 3;

    const __nv_bfloat16* __restrict__ Ah = (mode == 0) ? g_xh : g_Ch;
    const __nv_bfloat16* __restrict__ Al = (mode == 0) ? g_xl : g_Cl;
    const __nv_bfloat16* __restrict__ Bh = g_Bh + (size_t)zz * DM * DM;
    const __nv_bfloat16* __restrict__ Bl = g_Bl + (size_t)zz * DM * DM;

    float acc[4][4][4];
#pragma unroll
    for (int a = 0; a < 4; a++)
#pragma unroll
        for (int b = 0; b < 4; b++)
#pragma unroll
            for (int c = 0; c < 4; c++) acc[a][b][c] = 0.f;

    const int a_r  = (lane & 7) + ((lane >> 3) & 1) * 8;
    const int a_kc = (lane >> 4) * 8;
    const int b_n  = (lane & 7) + (lane >> 4) * 8;
    const int b_kc = ((lane >> 3) & 1) * 8;

#define LOAD_STAGE(it_)                                                          \
    do {                                                                         \
        int k0_ = (it_) * 32;                                                    \
        uint32_t sb_ = sm0 + ((it_) & 1) * MMSTAGE;                              \
        _Pragma("unroll")                                                        \
        for (int i_ = 0; i_ < 2; i_++) {                                         \
            int idx_ = tid + i_ * 256;                                           \
            int r_ = idx_ >> 2, sg_ = idx_ & 3;                                  \
            uint32_t doff_ = r_ * 80 + sg_ * 16;                                 \
            cpasync16(sb_ + doff_,              Ah + (size_t)(row0 + r_) * DM + k0_ + sg_ * 8); \
            cpasync16(sb_ + MMBUF + doff_,      Al + (size_t)(row0 + r_) * DM + k0_ + sg_ * 8); \
            cpasync16(sb_ + 2 * MMBUF + doff_,  Bh + (size_t)(col0 + r_) * DM + k0_ + sg_ * 8); \
            cpasync16(sb_ + 3 * MMBUF + doff_,  Bl + (size_t)(col0 + r_) * DM + k0_ + sg_ * 8); \
        }                                                                        \
    } while (0)

    LOAD_STAGE(0);
    CP_COMMIT();

    for (int it = 0; it < 32; it++) {
        CP_WAIT(0);               // stage it complete (only outstanding group)
        __syncthreads();          // visible to all; all warps done reading stage it-1
        if (it + 1 < 32) {
            LOAD_STAGE(it + 1);   // overwrites stage last read at it-1: safe post-barrier
            CP_COMMIT();
        }

        uint32_t sb = sm0 + (it & 1) * MMSTAGE;
#pragma unroll
        for (int kk = 0; kk < 2; kk++) {
            uint32_t bh[2][4], bl[2][4];
#pragma unroll
            for (int np = 0; np < 2; np++) {
                int n = warpN * 32 + np * 16 + b_n;
                uint32_t off = (uint32_t)(n * 80 + (kk * 16 + b_kc) * 2);
                ldsm4(bh[np], sb + 2 * MMBUF + off);
                ldsm4(bl[np], sb + 3 * MMBUF + off);
            }
            // A-fragments in groups of 2 m-tiles to cap live registers (~116)
#pragma unroll
            for (int mp = 0; mp < 2; mp++) {
                uint32_t ah[2][4], al[2][4];
#pragma unroll
                for (int mi = 0; mi < 2; mi++) {
                    int r = warpM * 64 + (mp * 2 + mi) * 16 + a_r;
                    uint32_t off = (uint32_t)(r * 80 + (kk * 16 + a_kc) * 2);
                    ldsm4(ah[mi], sb + off);
                    ldsm4(al[mi], sb + MMBUF + off);
                }
#pragma unroll
                for (int mi = 0; mi < 2; mi++)
#pragma unroll
                    for (int nb = 0; nb < 4; nb++) {
                        float* a = acc[mp * 2 + mi][nb];
                        const uint32_t* bhf = &bh[nb >> 1][(nb & 1) * 2];
                        const uint32_t* blf = &bl[nb >> 1][(nb & 1) * 2];
                        mma16816(a, ah[mi], bhf);
                        mma16816(a, ah[mi], blf);
                        mma16816(a, al[mi], bhf);
                    }
            }
        }
    }

    if (mode == 0) {
        __nv_bfloat16* __restrict__ Oh = (z == 0) ? g_Qh : (z == 1) ? g_Kh : g_Vh;
        __nv_bfloat16* __restrict__ Ol = (z == 0) ? g_Ql : (z == 1) ? g_Kl : g_Vl;
        const float sc = (z == 0) ? 0.125f : 1.0f;
#pragma unroll
        for (int mb = 0; mb < 4; mb++) {
            int r = row0 + warpM * 64 + mb * 16 + (lane >> 2);
#pragma unroll
            for (int nb = 0; nb < 4; nb++) {
                int c = col0 + warpN * 32 + nb * 8 + (lane & 3) * 2;
                float v0 = acc[mb][nb][0] * sc, v1 = acc[mb][nb][1] * sc;
                float v2 = acc[mb][nb][2] * sc, v3 = acc[mb][nb][3] * sc;
                uint32_t h01 = pkhi(v0, v1);
                uint32_t h23 = pkhi(v2, v3);
                *(uint32_t*)&Oh[(size_t)r * DM + c]       = h01;
                *(uint32_t*)&Ol[(size_t)r * DM + c]       = pklo(v0, v1, h01);
                *(uint32_t*)&Oh[(size_t)(r + 8) * DM + c] = h23;
                *(uint32_t*)&Ol[(size_t)(r + 8) * DM + c] = pklo(v2, v3, h23);
            }
        }
    } else {
#pragma unroll
        for (int mb = 0; mb < 4; mb++) {
            int r = row0 + warpM * 64 + mb * 16 + (lane >> 2);
#pragma unroll
            for (int nb = 0; nb < 4; nb++) {
                int c = col0 + warpN * 32 + nb * 8 + (lane & 3) * 2;
                float2 v0 = make_float2(acc[mb][nb][0] + bias[c], acc[mb][nb][1] + bias[c + 1]);
                float2 v1 = make_float2(acc[mb][nb][2] + bias[c], acc[mb][nb][3] + bias[c + 1]);
                *(float2*)&outp[(size_t)r * DM + c]       = v0;
                *(float2*)&outp[(size_t)(r + 8) * DM + c] = v1;
            }
        }
    }
#undef LOAD_STAGE
}

// ---------------------------------------------------------------------------
// HMMA flash attention, split-bf16 (3-term), cp.async double-buffered K/V,
// single barrier per chunk. Block 128 thr = 4 warps, 64-query tile.
// Writes Ch/Cl (split bf16).
// Smem (ATILE units): [Qh][Ql][Kh0][Kh1][Kl0][Kl1][Vh0][Vh1][Vl0][Vl1]
// ---------------------------------------------------------------------------
#define KST 72
#define ATILE (64 * KST)
#define ATB   (ATILE * 2)                        // bytes per tile (9216)
#define ATTN_SMEM (10 * ATB)                     // 92160

__global__ __launch_bounds__(128) void attn_kernel()
{
    extern __shared__ __nv_bfloat16 smb[];
    const uint32_t sm0 = smem_u32(smb);

    const int qt = blockIdx.x;
    const int bh = blockIdx.y;
    const int b  = bh >> 4;
    const int h  = bh & 15;
    const int tid  = threadIdx.x;
    const int w    = tid >> 5;
    const int lane = tid & 31;
    const int qs = qt * 64;

    const size_t hoff = (size_t)b * SEQ * DM + h * HD;
    const __nv_bfloat16* __restrict__ Qgh = g_Qh + hoff;
    const __nv_bfloat16* __restrict__ Qgl = g_Ql + hoff;
    const __nv_bfloat16* __restrict__ Kgh = g_Kh + hoff;
    const __nv_bfloat16* __restrict__ Kgl = g_Kl + hoff;
    const __nv_bfloat16* __restrict__ Vgh = g_Vh + hoff;
    const __nv_bfloat16* __restrict__ Vgl = g_Vl + hoff;

    int ks0 = qs - WIN; if (ks0 < 0) ks0 = 0;
    int ke  = qs + 64 + WIN; if (ke > SEQ) ke = SEQ;
    const int nc = (ke - ks0) >> 6;

#define PREF(ci_)                                                                \
    do {                                                                         \
        int kb_ = ks0 + (ci_) * 64;                                              \
        uint32_t st_ = ((ci_) & 1) * ATB;                                        \
        _Pragma("unroll")                                                        \
        for (int i_ = 0; i_ < 4; i_++) {                                         \
            int idx_ = tid + i_ * 128;                                           \
            int r_ = idx_ >> 3, c_ = idx_ & 7;                                   \
            uint32_t doff_ = (uint32_t)(r_ * KST + c_ * 8) * 2;                  \
            size_t g_ = (size_t)(kb_ + r_) * DM + c_ * 8;                        \
            cpasync16(sm0 + 2 * ATB + st_ + doff_, Kgh + g_);                    \
            cpasync16(sm0 + 4 * ATB + st_ + doff_, Kgl + g_);                    \
            cpasync16(sm0 + 6 * ATB + st_ + doff_, Vgh + g_);                    \
            cpasync16(sm0 + 8 * ATB + st_ + doff_, Vgl + g_);                    \
        }                                                                        \
    } while (0)

    PREF(0);
    CP_COMMIT();

    // load Q tile (64 rows x 64 bf16)
    for (int i = tid; i < 64 * 8; i += 128) {
        int r = i >> 3, c = i & 7;
        *(uint4*)&smb[r * KST + c * 8]         = *(const uint4*)(Qgh + (size_t)(qs + r) * DM + c * 8);
        *(uint4*)&smb[ATILE + r * KST + c * 8] = *(const uint4*)(Qgl + (size_t)(qs + r) * DM + c * 8);
    }
    __syncthreads();

    const int a_r  = (lane & 7) + ((lane >> 3) & 1) * 8;
    const int a_kc = (lane >> 4) * 8;
    uint32_t qa_h[4][4], qa_l[4][4];
#pragma unroll
    for (int kk = 0; kk < 4; kk++) {
        uint32_t off = (uint32_t)((w * 16 + a_r) * KST + kk * 16 + a_kc) * 2;
        ldsm4(qa_h[kk], sm0 + off);
        ldsm4(qa_l[kk], sm0 + ATB + off);
    }

    float O[8][4];
#pragma unroll
    for (int t = 0; t < 8; t++)
#pragma unroll
        for (int e = 0; e < 4; e++) O[t][e] = 0.f;
    float m0 = -1e30f, m1 = -1e30f, l0 = 0.f, l1 = 0.f;

    const int b_n  = (lane & 7) + (lane >> 4) * 8;
    const int b_kc = ((lane >> 3) & 1) * 8;
    const int v_r  = lane & 15;
    const int v_c  = (lane >> 4) * 8;
    const int q0 = qs + w * 16 + (lane >> 2);
    const int q1 = q0 + 8;

    for (int ci = 0; ci < nc; ci++) {
        const int kb = ks0 + ci * 64;
        CP_WAIT(0);                          // chunk ci complete (only group outstanding)
        __syncthreads();                     // visible; all warps done reading stage ci-1
        if (ci + 1 < nc) {
            PREF(ci + 1);                    // overwrites stage last read at ci-1: safe
            CP_COMMIT();
        }

        const uint32_t Khb = sm0 + 2 * ATB + (ci & 1) * ATB;
        const uint32_t Klb = sm0 + 4 * ATB + (ci & 1) * ATB;
        const uint32_t Vhb = sm0 + 6 * ATB + (ci & 1) * ATB;
        const uint32_t Vlb = sm0 + 8 * ATB + (ci & 1) * ATB;

        // ---- scores
        float S[8][4];
#pragma unroll
        for (int t = 0; t < 8; t++)
#pragma unroll
            for (int e = 0; e < 4; e++) S[t][e] = 0.f;

#pragma unroll
        for (int kk = 0; kk < 4; kk++) {
#pragma unroll
            for (int nt = 0; nt < 4; nt++) {
                uint32_t kh[4], kl[4];
                uint32_t off = (uint32_t)((nt * 16 + b_n) * KST + kk * 16 + b_kc) * 2;
                ldsm4(kh, Khb + off);
                ldsm4(kl, Klb + off);
#pragma unroll
                for (int half = 0; half < 2; half++) {
                    float* s = S[nt * 2 + half];
                    mma16816(s, qa_h[kk], &kh[half * 2]);
                    mma16816(s, qa_h[kk], &kl[half * 2]);
                    mma16816(s, qa_l[kk], &kh[half * 2]);
                }
            }
        }

        // ---- mask + online softmax
        const int kc = kb + 2 * (lane & 3);
        float mx0 = -1e30f, mx1 = -1e30f;
#pragma unroll
        for (int j = 0; j < 8; j++) {
            int d0 = kc + j * 8 - q0 + WIN;
            S[j][0] = ((unsigned)d0 <= 2u * WIN)       ? S[j][0] : -1e30f;
            S[j][1] = ((unsigned)(d0 + 1) <= 2u * WIN) ? S[j][1] : -1e30f;
            S[j][2] = ((unsigned)(d0 - 8) <= 2u * WIN) ? S[j][2] : -1e30f;
            S[j][3] = ((unsigned)(d0 - 7) <= 2u * WIN) ? S[j][3] : -1e30f;
            mx0 = fmaxf(mx0, fmaxf(S[j][0], S[j][1]));
            mx1 = fmaxf(mx1, fmaxf(S[j][2], S[j][3]));
        }
        mx0 = fmaxf(mx0, __shfl_xor_sync(0xffffffffu, mx0, 1));
        mx0 = fmaxf(mx0, __shfl_xor_sync(0xffffffffu, mx0, 2));
        mx1 = fmaxf(mx1, __shfl_xor_sync(0xffffffffu, mx1, 1));
        mx1 = fmaxf(mx1, __shfl_xor_sync(0xffffffffu, mx1, 2));

        float mn0 = fmaxf(m0, mx0), mn1 = fmaxf(m1, mx1);
        float f0 = __expf(m0 - mn0), f1 = __expf(m1 - mn1);
        float s0 = 0.f, s1 = 0.f;
#pragma unroll
        for (int j = 0; j < 8; j++) {
            S[j][0] = __expf(S[j][0] - mn0);
            S[j][1] = __expf(S[j][1] - mn0);
            S[j][2] = __expf(S[j][2] - mn1);
            S[j][3] = __expf(S[j][3] - mn1);
            s0 += S[j][0] + S[j][1];
            s1 += S[j][2] + S[j][3];
        }
        s0 += __shfl_xor_sync(0xffffffffu, s0, 1);
        s0 += __shfl_xor_sync(0xffffffffu, s0, 2);
        s1 += __shfl_xor_sync(0xffffffffu, s1, 1);
        s1 += __shfl_xor_sync(0xffffffffu, s1, 2);
        l0 = l0 * f0 + s0;  m0 = mn0;
        l1 = l1 * f1 + s1;  m1 = mn1;
#pragma unroll
        for (int t = 0; t < 8; t++) {
            O[t][0] *= f0; O[t][1] *= f0;
            O[t][2] *= f1; O[t][3] *= f1;
        }

        // ---- PV
#pragma unroll
        for (int kk = 0; kk < 4; kk++) {
            uint32_t pa_h[4], pa_l[4];
            const float* sj0 = S[2 * kk];
            const float* sj1 = S[2 * kk + 1];
            pa_h[0] = pkhi(sj0[0], sj0[1]);  pa_l[0] = pklo(sj0[0], sj0[1], pa_h[0]);
            pa_h[1] = pkhi(sj0[2], sj0[3]);  pa_l[1] = pklo(sj0[2], sj0[3], pa_h[1]);
            pa_h[2] = pkhi(sj1[0], sj1[1]);  pa_l[2] = pklo(sj1[0], sj1[1], pa_h[2]);
            pa_h[3] = pkhi(sj1[2], sj1[3]);  pa_l[3] = pklo(sj1[2], sj1[3], pa_h[3]);
#pragma unroll
            for (int nt = 0; nt < 4; nt++) {
                uint32_t vh[4], vl[4];
                uint32_t off = (uint32_t)((kk * 16 + v_r) * KST + nt * 16 + v_c) * 2;
                ldsm4t(vh, Vhb + off);
                ldsm4t(vl, Vlb + off);
#pragma unroll
                for (int half = 0; half < 2; half++) {
                    float* o = O[nt * 2 + half];
                    mma16816(o, pa_h, &vh[half * 2]);
                    mma16816(o, pa_l, &vh[half * 2]);
                    mma16816(o, pa_h, &vl[half * 2]);
                }
            }
        }
    }

    // ---- epilogue
    float inv0 = 1.f / l0, inv1 = 1.f / l1;
#pragma unroll
    for (int t = 0; t < 8; t++) {
        int c = h * HD + t * 8 + 2 * (lane & 3);
        float v0 = O[t][0] * inv0, v1 = O[t][1] * inv0;
        float v2 = O[t][2] * inv1, v3 = O[t][3] * inv1;
        size_t r0o = ((size_t)b * SEQ + q0) * DM + c;
        size_t r1o = ((size_t)b * SEQ + q1) * DM + c;
        uint32_t h01 = pkhi(v0, v1);
        uint32_t h23 = pkhi(v2, v3);
        *(uint32_t*)&g_Ch[r0o] = h01;
        *(uint32_t*)&g_Cl[r0o] = pklo(v0, v1, h01);
        *(uint32_t*)&g_Ch[r1o] = h23;
        *(uint32_t*)&g_Cl[r1o] = pklo(v2, v3, h23);
    }
#undef PREF
}

// ---------------------------------------------------------------------------
extern "C" void kernel_launch(void* const* d_in, const int* in_sizes, int n_in,
                              void* d_out, int out_size)
{
    const float* x  = (const float*)d_in[0];
    const float* Wq = (const float*)d_in[1];
    const float* Wk = (const float*)d_in[2];
    const float* Wv = (const float*)d_in[3];
    const float* Wo = (const float*)d_in[4];
    const float* bo = (const float*)d_in[5];
    float* out = (float*)d_out;

    cudaFuncSetAttribute(mm_kernel, cudaFuncAttributeMaxDynamicSharedMemorySize, MM_SMEM);
    cudaFuncSetAttribute(attn_kernel, cudaFuncAttributeMaxDynamicSharedMemorySize, ATTN_SMEM);

    split_kernel<<<(MROWS * DM) / (4 * 256), 256>>>(x);
    splitT_kernel<<<dim3(DM / 32, DM / 32, 4), dim3(32, 8)>>>(Wq, Wk, Wv, Wo);

    mm_kernel<<<dim3(DM / 128, MROWS / 128, 3), 256, MM_SMEM>>>(nullptr, nullptr, 0);

    attn_kernel<<<dim3(SEQ / 64, BATCH * NH), 128, ATTN_SMEM>>>();

    mm_kernel<<<dim3(DM / 128, MROWS / 128, 1), 256, MM_SMEM>>>(bo, out, 1);
}

// round 8
// speedup vs baseline: 1.1949x; 1.0317x over previous
#include <cuda_runtime.h>
#include <cuda_bf16.h>
#include <cstdint>

#define SEQ   2048
#define BATCH 2
#define NH    16
#define HD    64
#define DM    1024
#define WIN   256
#define MROWS (BATCH * SEQ)          // 4096

// ---------------------------------------------------------------------------
// Device scratch (allocation-guard-legal). All activations kept as split bf16.
// ---------------------------------------------------------------------------
__device__ __nv_bfloat16 g_xh[(size_t)MROWS * DM];
__device__ __nv_bfloat16 g_xl[(size_t)MROWS * DM];
__device__ __nv_bfloat16 g_Ch[(size_t)MROWS * DM];
__device__ __nv_bfloat16 g_Cl[(size_t)MROWS * DM];
__device__ __nv_bfloat16 g_Qh[(size_t)MROWS * DM];
__device__ __nv_bfloat16 g_Ql[(size_t)MROWS * DM];
__device__ __nv_bfloat16 g_Kh[(size_t)MROWS * DM];
__device__ __nv_bfloat16 g_Kl[(size_t)MROWS * DM];
__device__ __nv_bfloat16 g_Vh[(size_t)MROWS * DM];
__device__ __nv_bfloat16 g_Vl[(size_t)MROWS * DM];
__device__ __nv_bfloat16 g_Bh[(size_t)4 * DM * DM];   // W^T as [n][k]; q,k,v,o
__device__ __nv_bfloat16 g_Bl[(size_t)4 * DM * DM];

// ---------------------------------------------------------------------------
// PTX helpers (portable: sm_80+ tensor path, cp.async)
// ---------------------------------------------------------------------------
__device__ __forceinline__ uint32_t smem_u32(const void* p) {
    uint32_t a;
    asm("{ .reg .u64 t; cvta.to.shared.u64 t, %1; cvt.u32.u64 %0, t; }"
        : "=r"(a) : "l"(p));
    return a;
}

__device__ __forceinline__ void cpasync16(uint32_t dst, const void* src) {
    asm volatile("cp.async.cg.shared.global [%0], [%1], 16;"
                 :: "r"(dst), "l"(src));
}
#define CP_COMMIT() asm volatile("cp.async.commit_group;" ::: "memory")
#define CP_WAIT(n)  asm volatile("cp.async.wait_group %0;" :: "n"(n) : "memory")

__device__ __forceinline__ void ldsm4(uint32_t* r, uint32_t addr) {
    asm volatile("ldmatrix.sync.aligned.m8n8.x4.shared.b16 {%0,%1,%2,%3}, [%4];"
                 : "=r"(r[0]), "=r"(r[1]), "=r"(r[2]), "=r"(r[3]) : "r"(addr));
}
__device__ __forceinline__ void ldsm4t(uint32_t* r, uint32_t addr) {
    asm volatile("ldmatrix.sync.aligned.m8n8.x4.trans.shared.b16 {%0,%1,%2,%3}, [%4];"
                 : "=r"(r[0]), "=r"(r[1]), "=r"(r[2]), "=r"(r[3]) : "r"(addr));
}

__device__ __forceinline__ void mma16816(float* c, const uint32_t* a, const uint32_t* b) {
    asm volatile(
        "mma.sync.aligned.m16n8k16.row.col.f32.bf16.bf16.f32 "
        "{%0,%1,%2,%3}, {%4,%5,%6,%7}, {%8,%9}, {%0,%1,%2,%3};"
        : "+f"(c[0]), "+f"(c[1]), "+f"(c[2]), "+f"(c[3])
        : "r"(a[0]), "r"(a[1]), "r"(a[2]), "r"(a[3]), "r"(b[0]), "r"(b[1]));
}

__device__ __forceinline__ uint32_t pkhi(float a, float b) {
    __nv_bfloat162 t = __floats2bfloat162_rn(a, b);
    return *reinterpret_cast<uint32_t*>(&t);
}
__device__ __forceinline__ uint32_t pklo(float a, float b, uint32_t hi) {
    __nv_bfloat162 h = *reinterpret_cast<__nv_bfloat162*>(&hi);
    return pkhi(a - __bfloat162float(h.x), b - __bfloat162float(h.y));
}

// ---------------------------------------------------------------------------
// Split fp32 x -> bf16 hi/lo
// ---------------------------------------------------------------------------
__global__ __launch_bounds__(256) void split_kernel(const float* __restrict__ src)
{
    int i = blockIdx.x * 256 + threadIdx.x;
    float4 v = ((const float4*)src)[i];
    uint32_t h01 = pkhi(v.x, v.y);
    uint32_t h23 = pkhi(v.z, v.w);
    ((uint32_t*)g_xh)[2 * i]     = h01;
    ((uint32_t*)g_xh)[2 * i + 1] = h23;
    ((uint32_t*)g_xl)[2 * i]     = pklo(v.x, v.y, h01);
    ((uint32_t*)g_xl)[2 * i + 1] = pklo(v.z, v.w, h23);
}

// Split + transpose weights: g_B*[z][n][k] = W_z[k][n]
__global__ __launch_bounds__(256) void splitT_kernel(
    const float* __restrict__ w0, const float* __restrict__ w1,
    const float* __restrict__ w2, const float* __restrict__ w3)
{
    __shared__ float t[32][33];
    const int z = blockIdx.z;
    const float* __restrict__ W = (z == 0) ? w0 : (z == 1) ? w1 : (z == 2) ? w2 : w3;
    const int tx = threadIdx.x, ty = threadIdx.y;
    const int bx = blockIdx.x, by = blockIdx.y;
#pragma unroll
    for (int i = 0; i < 4; i++) {
        int k = by * 32 + ty + i * 8;
        int n = bx * 32 + tx;
        t[ty + i * 8][tx] = W[(size_t)k * DM + n];
    }
    __syncthreads();
    size_t base = (size_t)z * DM * DM;
#pragma unroll
    for (int i = 0; i < 4; i++) {
        int n = bx * 32 + ty + i * 8;
        int k = by * 32 + tx;
        float v = t[tx][ty + i * 8];
        __nv_bfloat16 h = __float2bfloat16(v);
        g_Bh[base + (size_t)n * DM + k] = h;
        g_Bl[base + (size_t)n * DM + k] = __float2bfloat16(v - __bfloat162float(h));
    }
}

// ---------------------------------------------------------------------------
// Split-bf16 HMMA GEMM. CTA 128x128, kTile 32, 2-stage cp.async,
// single barrier per iteration. __launch_bounds__(256,2): 2 CTAs/SM.
// mode 0: x -> Qh/Ql, Kh/Kl, Vh/Vl (Q scaled 1/8). mode 1: C -> out (+bias).
// ---------------------------------------------------------------------------
#define MMBUF   10240                      // 128 rows * 80 B
#define MMSTAGE (4 * MMBUF)                // Ah, Al, Bh, Bl  (40960)
#define MM_SMEM (2 * MMSTAGE)              // 81920

__global__ __launch_bounds__(256, 2) void mm_kernel(
    const float* __restrict__ bias, float* __restrict__ outp, int mode)
{
    extern __shared__ char smc[];
    const uint32_t sm0 = smem_u32(smc);
    const int tid  = threadIdx.x;
    const int lane = tid & 31;
    const int wid  = tid >> 5;
    const int warpM = wid & 1;
    const int warpN = wid >> 1;
    const int row0 = blockIdx.y * 128;
    const int col0 = blockIdx.x * 128;
    const int z    = blockIdx.z;
    const int zz   = (mode == 0) ? z : 3;

    const __nv_bfloat16* __restrict__ Ah = (mode == 0) ? g_xh : g_Ch;
    const __nv_bfloat16* __restrict__ Al = (mode == 0) ? g_xl : g_Cl;
    const __nv_bfloat16* __restrict__ Bh = g_Bh + (size_t)zz * DM * DM;
    const __nv_bfloat16* __restrict__ Bl = g_Bl + (size_t)zz * DM * DM;

    float acc[4][4][4];
#pragma unroll
    for (int a = 0; a < 4; a++)
#pragma unroll
        for (int b = 0; b < 4; b++)
#pragma unroll
            for (int c = 0; c < 4; c++) acc[a][b][c] = 0.f;

    const int a_r  = (lane & 7) + ((lane >> 3) & 1) * 8;
    const int a_kc = (lane >> 4) * 8;
    const int b_n  = (lane & 7) + (lane >> 4) * 8;
    const int b_kc = ((lane >> 3) & 1) * 8;

#define LOAD_STAGE(it_)                                                          \
    do {                                                                         \
        int k0_ = (it_) * 32;                                                    \
        uint32_t sb_ = sm0 + ((it_) & 1) * MMSTAGE;                              \
        _Pragma("unroll")                                                        \
        for (int i_ = 0; i_ < 2; i_++) {                                         \
            int idx_ = tid + i_ * 256;                                           \
            int r_ = idx_ >> 2, sg_ = idx_ & 3;                                  \
            uint32_t doff_ = r_ * 80 + sg_ * 16;                                 \
            cpasync16(sb_ + doff_,              Ah + (size_t)(row0 + r_) * DM + k0_ + sg_ * 8); \
            cpasync16(sb_ + MMBUF + doff_,      Al + (size_t)(row0 + r_) * DM + k0_ + sg_ * 8); \
            cpasync16(sb_ + 2 * MMBUF + doff_,  Bh + (size_t)(col0 + r_) * DM + k0_ + sg_ * 8); \
            cpasync16(sb_ + 3 * MMBUF + doff_,  Bl + (size_t)(col0 + r_) * DM + k0_ + sg_ * 8); \
        }                                                                        \
    } while (0)

    LOAD_STAGE(0);
    CP_COMMIT();

    for (int it = 0; it < 32; it++) {
        CP_WAIT(0);
        __syncthreads();
        if (it + 1 < 32) {
            LOAD_STAGE(it + 1);
            CP_COMMIT();
        }

        uint32_t sb = sm0 + (it & 1) * MMSTAGE;
#pragma unroll
        for (int kk = 0; kk < 2; kk++) {
            uint32_t bh[2][4], bl[2][4];
#pragma unroll
            for (int np = 0; np < 2; np++) {
                int n = warpN * 32 + np * 16 + b_n;
                uint32_t off = (uint32_t)(n * 80 + (kk * 16 + b_kc) * 2);
                ldsm4(bh[np], sb + 2 * MMBUF + off);
                ldsm4(bl[np], sb + 3 * MMBUF + off);
            }
#pragma unroll
            for (int mp = 0; mp < 2; mp++) {
                uint32_t ah[2][4], al[2][4];
#pragma unroll
                for (int mi = 0; mi < 2; mi++) {
                    int r = warpM * 64 + (mp * 2 + mi) * 16 + a_r;
                    uint32_t off = (uint32_t)(r * 80 + (kk * 16 + a_kc) * 2);
                    ldsm4(ah[mi], sb + off);
                    ldsm4(al[mi], sb + MMBUF + off);
                }
#pragma unroll
                for (int mi = 0; mi < 2; mi++)
#pragma unroll
                    for (int nb = 0; nb < 4; nb++) {
                        float* a = acc[mp * 2 + mi][nb];
                        const uint32_t* bhf = &bh[nb >> 1][(nb & 1) * 2];
                        const uint32_t* blf = &bl[nb >> 1][(nb & 1) * 2];
                        mma16816(a, ah[mi], bhf);
                        mma16816(a, ah[mi], blf);
                        mma16816(a, al[mi], bhf);
                    }
            }
        }
    }

    if (mode == 0) {
        __nv_bfloat16* __restrict__ Oh = (z == 0) ? g_Qh : (z == 1) ? g_Kh : g_Vh;
        __nv_bfloat16* __restrict__ Ol = (z == 0) ? g_Ql : (z == 1) ? g_Kl : g_Vl;
        const float sc = (z == 0) ? 0.125f : 1.0f;
#pragma unroll
        for (int mb = 0; mb < 4; mb++) {
            int r = row0 + warpM * 64 + mb * 16 + (lane >> 2);
#pragma unroll
            for (int nb = 0; nb < 4; nb++) {
                int c = col0 + warpN * 32 + nb * 8 + (lane & 3) * 2;
                float v0 = acc[mb][nb][0] * sc, v1 = acc[mb][nb][1] * sc;
                float v2 = acc[mb][nb][2] * sc, v3 = acc[mb][nb][3] * sc;
                uint32_t h01 = pkhi(v0, v1);
                uint32_t h23 = pkhi(v2, v3);
                *(uint32_t*)&Oh[(size_t)r * DM + c]       = h01;
                *(uint32_t*)&Ol[(size_t)r * DM + c]       = pklo(v0, v1, h01);
                *(uint32_t*)&Oh[(size_t)(r + 8) * DM + c] = h23;
                *(uint32_t*)&Ol[(size_t)(r + 8) * DM + c] = pklo(v2, v3, h23);
            }
        }
    } else {
#pragma unroll
        for (int mb = 0; mb < 4; mb++) {
            int r = row0 + warpM * 64 + mb * 16 + (lane >> 2);
#pragma unroll
            for (int nb = 0; nb < 4; nb++) {
                int c = col0 + warpN * 32 + nb * 8 + (lane & 3) * 2;
                float2 v0 = make_float2(acc[mb][nb][0] + bias[c], acc[mb][nb][1] + bias[c + 1]);
                float2 v1 = make_float2(acc[mb][nb][2] + bias[c], acc[mb][nb][3] + bias[c + 1]);
                *(float2*)&outp[(size_t)r * DM + c]       = v0;
                *(float2*)&outp[(size_t)(r + 8) * DM + c] = v1;
            }
        }
    }
#undef LOAD_STAGE
}

// ---------------------------------------------------------------------------
// HMMA flash attention, split-bf16 (3-term), split-KEY warp specialization.
// 256 thr = 8 warps per 64-query tile: warp (wq = w&3, wk = w>>2) handles
// queries wq*16..+15 x keys wk*32..+31 of each 64-key chunk, with an
// INDEPENDENT online softmax per warp; the two key-halves merge once at end.
// cp.async double-buffered K/V, single barrier per chunk. Writes Ch/Cl.
// ---------------------------------------------------------------------------
#define KST 72
#define ATILE (64 * KST)
#define ATB   (ATILE * 2)                        // bytes per tile (9216)
#define ATTN_SMEM (10 * ATB)                     // 92160

__global__ __launch_bounds__(256, 2) void attn_kernel()
{
    extern __shared__ __nv_bfloat16 smb[];
    const uint32_t sm0 = smem_u32(smb);

    const int qt = blockIdx.x;
    const int bh = blockIdx.y;
    const int b  = bh >> 4;
    const int h  = bh & 15;
    const int tid  = threadIdx.x;
    const int w    = tid >> 5;
    const int wq   = w & 3;              // query quarter
    const int wk   = w >> 2;             // key half
    const int lane = tid & 31;
    const int qs = qt * 64;

    const size_t hoff = (size_t)b * SEQ * DM + h * HD;
    const __nv_bfloat16* __restrict__ Qgh = g_Qh + hoff;
    const __nv_bfloat16* __restrict__ Qgl = g_Ql + hoff;
    const __nv_bfloat16* __restrict__ Kgh = g_Kh + hoff;
    const __nv_bfloat16* __restrict__ Kgl = g_Kl + hoff;
    const __nv_bfloat16* __restrict__ Vgh = g_Vh + hoff;
    const __nv_bfloat16* __restrict__ Vgl = g_Vl + hoff;

    int ks0 = qs - WIN; if (ks0 < 0) ks0 = 0;
    int ke  = qs + 64 + WIN; if (ke > SEQ) ke = SEQ;
    const int nc = (ke - ks0) >> 6;

#define PREF(ci_)                                                                \
    do {                                                                         \
        int kb_ = ks0 + (ci_) * 64;                                              \
        uint32_t st_ = ((ci_) & 1) * ATB;                                        \
        _Pragma("unroll")                                                        \
        for (int i_ = 0; i_ < 2; i_++) {                                         \
            int idx_ = tid + i_ * 256;                                           \
            int r_ = idx_ >> 3, c_ = idx_ & 7;                                   \
            uint32_t doff_ = (uint32_t)(r_ * KST + c_ * 8) * 2;                  \
            size_t g_ = (size_t)(kb_ + r_) * DM + c_ * 8;                        \
            cpasync16(sm0 + 2 * ATB + st_ + doff_, Kgh + g_);                    \
            cpasync16(sm0 + 4 * ATB + st_ + doff_, Kgl + g_);                    \
            cpasync16(sm0 + 6 * ATB + st_ + doff_, Vgh + g_);                    \
            cpasync16(sm0 + 8 * ATB + st_ + doff_, Vgl + g_);                    \
        }                                                                        \
    } while (0)

    PREF(0);
    CP_COMMIT();

    // load Q tile (64 rows x 64 bf16)
    for (int i = tid; i < 64 * 8; i += 256) {
        int r = i >> 3, c = i & 7;
        *(uint4*)&smb[r * KST + c * 8]         = *(const uint4*)(Qgh + (size_t)(qs + r) * DM + c * 8);
        *(uint4*)&smb[ATILE + r * KST + c * 8] = *(const uint4*)(Qgl + (size_t)(qs + r) * DM + c * 8);
    }
    __syncthreads();

    const int a_r  = (lane & 7) + ((lane >> 3) & 1) * 8;
    const int a_kc = (lane >> 4) * 8;
    uint32_t qa_h[4][4], qa_l[4][4];
#pragma unroll
    for (int kk = 0; kk < 4; kk++) {
        uint32_t off = (uint32_t)((wq * 16 + a_r) * KST + kk * 16 + a_kc) * 2;
        ldsm4(qa_h[kk], sm0 + off);
        ldsm4(qa_l[kk], sm0 + ATB + off);
    }

    float O[8][4];
#pragma unroll
    for (int t = 0; t < 8; t++)
#pragma unroll
        for (int e = 0; e < 4; e++) O[t][e] = 0.f;
    float m0 = -1e30f, m1 = -1e30f, l0 = 0.f, l1 = 0.f;

    const int b_n  = (lane & 7) + (lane >> 4) * 8;
    const int b_kc = ((lane >> 3) & 1) * 8;
    const int v_r  = lane & 15;
    const int v_c  = (lane >> 4) * 8;
    const int q0 = qs + wq * 16 + (lane >> 2);
    const int q1 = q0 + 8;

    for (int ci = 0; ci < nc; ci++) {
        const int kb = ks0 + ci * 64;
        CP_WAIT(0);
        __syncthreads();
        if (ci + 1 < nc) {
            PREF(ci + 1);
            CP_COMMIT();
        }

        const uint32_t Khb = sm0 + 2 * ATB + (ci & 1) * ATB;
        const uint32_t Klb = sm0 + 4 * ATB + (ci & 1) * ATB;
        const uint32_t Vhb = sm0 + 6 * ATB + (ci & 1) * ATB;
        const uint32_t Vlb = sm0 + 8 * ATB + (ci & 1) * ATB;

        // ---- scores: warp's 16q x 32k slab (keys wk*32 .. +31)
        float S[4][4];
#pragma unroll
        for (int t = 0; t < 4; t++)
#pragma unroll
            for (int e = 0; e < 4; e++) S[t][e] = 0.f;

#pragma unroll
        for (int kk = 0; kk < 4; kk++) {
#pragma unroll
            for (int nt = 0; nt < 2; nt++) {
                uint32_t kh[4], kl[4];
                uint32_t off = (uint32_t)((wk * 32 + nt * 16 + b_n) * KST + kk * 16 + b_kc) * 2;
                ldsm4(kh, Khb + off);
                ldsm4(kl, Klb + off);
#pragma unroll
                for (int half = 0; half < 2; half++) {
                    float* s = S[nt * 2 + half];
                    mma16816(s, qa_h[kk], &kh[half * 2]);
                    mma16816(s, qa_h[kk], &kl[half * 2]);
                    mma16816(s, qa_l[kk], &kh[half * 2]);
                }
            }
        }

        // ---- mask + online softmax (per-warp independent)
        const int kc = kb + wk * 32 + 2 * (lane & 3);
        float mx0 = -1e30f, mx1 = -1e30f;
#pragma unroll
        for (int j = 0; j < 4; j++) {
            int d0 = kc + j * 8 - q0 + WIN;
            S[j][0] = ((unsigned)d0 <= 2u * WIN)       ? S[j][0] : -1e30f;
            S[j][1] = ((unsigned)(d0 + 1) <= 2u * WIN) ? S[j][1] : -1e30f;
            S[j][2] = ((unsigned)(d0 - 8) <= 2u * WIN) ? S[j][2] : -1e30f;
            S[j][3] = ((unsigned)(d0 - 7) <= 2u * WIN) ? S[j][3] : -1e30f;
            mx0 = fmaxf(mx0, fmaxf(S[j][0], S[j][1]));
            mx1 = fmaxf(mx1, fmaxf(S[j][2], S[j][3]));
        }
        mx0 = fmaxf(mx0, __shfl_xor_sync(0xffffffffu, mx0, 1));
        mx0 = fmaxf(mx0, __shfl_xor_sync(0xffffffffu, mx0, 2));
        mx1 = fmaxf(mx1, __shfl_xor_sync(0xffffffffu, mx1, 1));
        mx1 = fmaxf(mx1, __shfl_xor_sync(0xffffffffu, mx1, 2));

        float mn0 = fmaxf(m0, mx0), mn1 = fmaxf(m1, mx1);
        float f0 = __expf(m0 - mn0), f1 = __expf(m1 - mn1);
        float s0 = 0.f, s1 = 0.f;
#pragma unroll
        for (int j = 0; j < 4; j++) {
            S[j][0] = __expf(S[j][0] - mn0);
            S[j][1] = __expf(S[j][1] - mn0);
            S[j][2] = __expf(S[j][2] - mn1);
            S[j][3] = __expf(S[j][3] - mn1);
            s0 += S[j][0] + S[j][1];
            s1 += S[j][2] + S[j][3];
        }
        s0 += __shfl_xor_sync(0xffffffffu, s0, 1);
        s0 += __shfl_xor_sync(0xffffffffu, s0, 2);
        s1 += __shfl_xor_sync(0xffffffffu, s1, 1);
        s1 += __shfl_xor_sync(0xffffffffu, s1, 2);
        l0 = l0 * f0 + s0;  m0 = mn0;
        l1 = l1 * f1 + s1;  m1 = mn1;
#pragma unroll
        for (int t = 0; t < 8; t++) {
            O[t][0] *= f0; O[t][1] *= f0;
            O[t][2] *= f1; O[t][3] *= f1;
        }

        // ---- PV over warp's 32 keys (two 16-key steps)
#pragma unroll
        for (int kk = 0; kk < 2; kk++) {
            uint32_t pa_h[4], pa_l[4];
            const float* sj0 = S[2 * kk];
            const float* sj1 = S[2 * kk + 1];
            pa_h[0] = pkhi(sj0[0], sj0[1]);  pa_l[0] = pklo(sj0[0], sj0[1], pa_h[0]);
            pa_h[1] = pkhi(sj0[2], sj0[3]);  pa_l[1] = pklo(sj0[2], sj0[3], pa_h[1]);
            pa_h[2] = pkhi(sj1[0], sj1[1]);  pa_l[2] = pklo(sj1[0], sj1[1], pa_h[2]);
            pa_h[3] = pkhi(sj1[2], sj1[3]);  pa_l[3] = pklo(sj1[2], sj1[3], pa_h[3]);
#pragma unroll
            for (int nt = 0; nt < 4; nt++) {
                uint32_t vh[4], vl[4];
                uint32_t off = (uint32_t)((wk * 32 + kk * 16 + v_r) * KST + nt * 16 + v_c) * 2;
                ldsm4t(vh, Vhb + off);
                ldsm4t(vl, Vlb + off);
#pragma unroll
                for (int half = 0; half < 2; half++) {
                    float* o = O[nt * 2 + half];
                    mma16816(o, pa_h, &vh[half * 2]);
                    mma16816(o, pa_l, &vh[half * 2]);
                    mma16816(o, pa_h, &vl[half * 2]);
                }
            }
        }
    }

    // ---- split-key merge: warps (wq, wk=1) publish; warps (wq, wk=0) combine
    __syncthreads();                                   // done with K/V smem
    float* mrg = (float*)smb;                          // 128 slots * 37 floats
    const int slot = (wq * 32 + lane) * 37;
    if (wk == 1) {
        mrg[slot + 0] = m0; mrg[slot + 1] = m1;
        mrg[slot + 2] = l0; mrg[slot + 3] = l1;
#pragma unroll
        for (int t = 0; t < 8; t++)
#pragma unroll
            for (int e = 0; e < 4; e++) mrg[slot + 4 + t * 4 + e] = O[t][e];
    }
    __syncthreads();
    if (wk == 0) {
        float pm0 = mrg[slot + 0], pm1 = mrg[slot + 1];
        float pl0 = mrg[slot + 2], pl1 = mrg[slot + 3];
        float M0 = fmaxf(m0, pm0), M1 = fmaxf(m1, pm1);
        float a0 = __expf(m0 - M0), b0 = __expf(pm0 - M0);
        float a1 = __expf(m1 - M1), b1 = __expf(pm1 - M1);
        float L0 = l0 * a0 + pl0 * b0;
        float L1 = l1 * a1 + pl1 * b1;
        float inv0 = 1.f / L0, inv1 = 1.f / L1;
#pragma unroll
        for (int t = 0; t < 8; t++) {
            float v0 = (O[t][0] * a0 + mrg[slot + 4 + t * 4 + 0] * b0) * inv0;
            float v1 = (O[t][1] * a0 + mrg[slot + 4 + t * 4 + 1] * b0) * inv0;
            float v2 = (O[t][2] * a1 + mrg[slot + 4 + t * 4 + 2] * b1) * inv1;
            float v3 = (O[t][3] * a1 + mrg[slot + 4 + t * 4 + 3] * b1) * inv1;
            int c = h * HD + t * 8 + 2 * (lane & 3);
            size_t r0o = ((size_t)b * SEQ + q0) * DM + c;
            size_t r1o = ((size_t)b * SEQ + q1) * DM + c;
            uint32_t h01 = pkhi(v0, v1);
            uint32_t h23 = pkhi(v2, v3);
            *(uint32_t*)&g_Ch[r0o] = h01;
            *(uint32_t*)&g_Cl[r0o] = pklo(v0, v1, h01);
            *(uint32_t*)&g_Ch[r1o] = h23;
            *(uint32_t*)&g_Cl[r1o] = pklo(v2, v3, h23);
        }
    }
#undef PREF
}

// ---------------------------------------------------------------------------
extern "C" void kernel_launch(void* const* d_in, const int* in_sizes, int n_in,
                              void* d_out, int out_size)
{
    const float* x  = (const float*)d_in[0];
    const float* Wq = (const float*)d_in[1];
    const float* Wk = (const float*)d_in[2];
    const float* Wv = (const float*)d_in[3];
    const float* Wo = (const float*)d_in[4];
    const float* bo = (const float*)d_in[5];
    float* out = (float*)d_out;

    cudaFuncSetAttribute(mm_kernel, cudaFuncAttributeMaxDynamicSharedMemorySize, MM_SMEM);
    cudaFuncSetAttribute(attn_kernel, cudaFuncAttributeMaxDynamicSharedMemorySize, ATTN_SMEM);

    split_kernel<<<(MROWS * DM) / (4 * 256), 256>>>(x);
    splitT_kernel<<<dim3(DM / 32, DM / 32, 4), dim3(32, 8)>>>(Wq, Wk, Wv, Wo);

    mm_kernel<<<dim3(DM / 128, MROWS / 128, 3), 256, MM_SMEM>>>(nullptr, nullptr, 0);

    attn_kernel<<<dim3(SEQ / 64, BATCH * NH), 256, ATTN_SMEM>>>();

    mm_kernel<<<dim3(DM / 128, MROWS / 128, 1), 256, MM_SMEM>>>(bo, out, 1);
}